// round 5
// baseline (speedup 1.0000x reference)
#include <cuda_runtime.h>
#include <cstdint>

// Problem constants
#define N_NODES 2048
#define NF4     512             // N_NODES/4 float4 columns
#define K_TOTAL 3072            // B*L
#define KC      128             // k rows per block
#define NKC     24              // k chunks (KC*NKC == K_TOTAL)
#define NBN     8               // n blocks (64 f4 cols each)
#define ROWS    3072

// Scratch device globals (no allocation allowed). Fully overwritten each launch.
__device__ float g_part[NKC * 8 * N_NODES];   // 1.5 MB partial conv sums
__device__ float g_per_node[N_NODES];         // 8 KB per-node scalars

// ---- helpers ---------------------------------------------------------------
__device__ __forceinline__ float4 ldg4v(const float4* p) {
    float4 v;
    asm volatile("ld.global.nc.v4.f32 {%0,%1,%2,%3}, [%4];"
                 : "=f"(v.x), "=f"(v.y), "=f"(v.z), "=f"(v.w) : "l"(p));
    return v;
}
__device__ __forceinline__ float ldg1v(const float* p) {
    float v;
    asm volatile("ld.global.nc.f32 %0, [%1];" : "=f"(v) : "l"(p));
    return v;
}
__device__ __forceinline__ unsigned long long pack2(float a, float b) {
    unsigned long long r;
    asm("mov.b64 %0, {%1, %2};" : "=l"(r) : "f"(a), "f"(b));
    return r;
}
// NON-volatile fma: scheduler may slide these into load shadows.
__device__ __forceinline__ void fma2n(unsigned long long& d,
                                      unsigned long long a,
                                      unsigned long long b) {
    asm("fma.rn.f32x2 %0, %1, %2, %0;" : "+l"(d) : "l"(a), "l"(b));
}
__device__ __forceinline__ void unpack2(unsigned long long v, float& a, float& b) {
    asm("mov.b64 {%0, %1}, %2;" : "=f"(a), "=f"(b) : "l"(v));
}
__device__ __forceinline__ unsigned smem_u32(const void* p) {
    unsigned a;
    asm("{ .reg .u64 t; cvta.to.shared.u64 t, %1; cvt.u32.u64 %0, t; }"
        : "=r"(a) : "l"(p));
    return a;
}

// ---------------------------------------------------------------------------
// K1: partial skinny GEMM, software-pipelined.
// Block = 64 f4-cols x 4 k-quarters (KC=128 rows). Thread: one f4 column over
// 32 k-rows, double-buffered 8-deep volatile LDG batches; FMAs fill the load
// shadow. w read as LDS.128 pairs. grid = (8, 24) x 256 threads.
// ---------------------------------------------------------------------------
__global__ __launch_bounds__(256, 2) void k_gemm_partial(
    const float4* __restrict__ x4, const float* __restrict__ Wc)
{
    __shared__ alignas(16) float sWd[KC * 8 * 2];   // 8 KB: Wc dup'd into f32x2
    __shared__ float4 sred[3 * 64 * 8];             // 24 KB: quarter partials

    const int tid  = threadIdx.x;
    const int ln   = tid & 63;
    const int q    = tid >> 6;
    const int nblk = blockIdx.x;
    const int kblk = blockIdx.y;

    const float* wsrc = Wc + (size_t)kblk * KC * 8;
    #pragma unroll
    for (int i = tid; i < KC * 8 * 2; i += 256) sWd[i] = wsrc[i >> 1];
    __syncthreads();

    const int c  = nblk * 64 + ln;
    const int kq = q * 32;
    const float4* xp = x4 + ((size_t)kblk * KC + kq) * NF4 + c;
    const ulonglong2* wp =
        reinterpret_cast<const ulonglong2*>(sWd) + (size_t)kq * 4;

    unsigned long long accp[2][8];
    #pragma unroll
    for (int p = 0; p < 2; p++)
        #pragma unroll
        for (int j = 0; j < 8; j++) accp[p][j] = 0ull;

    float4 bufA[8], bufB[8];

    // prologue: batch 0 loads
    #pragma unroll
    for (int u = 0; u < 8; u++)
        bufA[u] = ldg4v(xp + (size_t)u * NF4);

    #pragma unroll
    for (int b = 0; b < 4; b++) {
        float4* cur = (b & 1) ? bufB : bufA;
        float4* nxt = (b & 1) ? bufA : bufB;
        if (b < 3) {
            #pragma unroll
            for (int u = 0; u < 8; u++)            // prefetch next batch
                nxt[u] = ldg4v(xp + (size_t)((b + 1) * 8 + u) * NF4);
        }
        #pragma unroll
        for (int u = 0; u < 8; u++) {              // consume current batch
            unsigned long long lo = pack2(cur[u].x, cur[u].y);
            unsigned long long hi = pack2(cur[u].z, cur[u].w);
            const ulonglong2* w = wp + (b * 8 + u) * 4;
            #pragma unroll
            for (int jj = 0; jj < 4; jj++) {
                ulonglong2 wv = w[jj];             // LDS.128: two j weights
                fma2n(accp[0][2 * jj],     lo, wv.x);
                fma2n(accp[1][2 * jj],     hi, wv.x);
                fma2n(accp[0][2 * jj + 1], lo, wv.y);
                fma2n(accp[1][2 * jj + 1], hi, wv.y);
            }
        }
    }

    if (q != 0) {
        float4* dst = sred + (size_t)(q - 1) * 64 * 8 + ln * 8;
        #pragma unroll
        for (int j = 0; j < 8; j++) {
            float4 o;
            unpack2(accp[0][j], o.x, o.y);
            unpack2(accp[1][j], o.z, o.w);
            dst[j] = o;
        }
    }
    __syncthreads();
    if (q == 0) {
        float4* gp4 = reinterpret_cast<float4*>(g_part);
        #pragma unroll
        for (int j = 0; j < 8; j++) {
            float4 o;
            unpack2(accp[0][j], o.x, o.y);
            unpack2(accp[1][j], o.z, o.w);
            #pragma unroll
            for (int s = 0; s < 3; s++) {
                float4 r = sred[(size_t)s * 64 * 8 + ln * 8 + j];
                o.x += r.x; o.y += r.y; o.z += r.z; o.w += r.w;
            }
            gp4[(size_t)(kblk * 8 + j) * NF4 + c] = o;
        }
    }
}

// ---------------------------------------------------------------------------
// K2: reduce 24 partials per (n,j), add bc, folded MLP, write per_node[n].
// grid = 32 x 256; block = 64 nodes x 4 k-slices (6 chunks each).
// ---------------------------------------------------------------------------
__global__ __launch_bounds__(256) void k_reduce_mlp(
    const float* __restrict__ bc, const float* __restrict__ W1,
    const float* __restrict__ b1, const float* __restrict__ W2,
    const float* __restrict__ b2)
{
    __shared__ float sWeff[256];
    __shared__ float sb1[32];
    __shared__ float sW2v[32];
    __shared__ float sred[3 * 64 * 9];

    const int tid = threadIdx.x;
    const int ln  = tid & 63;
    const int q   = tid >> 6;
    const int n   = blockIdx.x * 64 + ln;

    sWeff[tid] = W1[tid] + W1[tid + 256];
    if (tid < 32) { sb1[tid] = b1[tid]; sW2v[tid] = W2[tid]; }

    float conv[8];
    #pragma unroll
    for (int j = 0; j < 8; j++) conv[j] = 0.0f;

    const int kc0 = q * 6;
    #pragma unroll
    for (int kc = kc0; kc < kc0 + 6; kc++) {
        const float* p = g_part + (size_t)(kc * 8) * N_NODES + n;
        float v[8];
        #pragma unroll
        for (int j = 0; j < 8; j++)
            v[j] = ldg1v(p + (size_t)j * N_NODES);
        #pragma unroll
        for (int j = 0; j < 8; j++) conv[j] += v[j];
    }

    if (q != 0) {
        #pragma unroll
        for (int j = 0; j < 8; j++)
            sred[(size_t)(q - 1) * 64 * 9 + ln * 9 + j] = conv[j];
    }
    __syncthreads();
    if (q == 0) {
        #pragma unroll
        for (int j = 0; j < 8; j++) {
            #pragma unroll
            for (int s = 0; s < 3; s++)
                conv[j] += sred[(size_t)s * 64 * 9 + ln * 9 + j];
            conv[j] += __ldg(bc + j);
        }

        float pn = __ldg(b2);
        #pragma unroll 4
        for (int m = 0; m < 32; m++) {
            float h = sb1[m];
            #pragma unroll
            for (int j = 0; j < 8; j++)
                h = fmaf(conv[j], sWeff[j * 32 + m], h);
            h = fmaxf(h, 0.01f * h);
            pn = fmaf(h, sW2v[m], pn);
        }
        g_per_node[n] = pn;
    }
}

// ---------------------------------------------------------------------------
// K3: broadcast via async bulk stores. Each block stages the 8KB per_node row
// in SMEM, then one thread issues 24 cp.async.bulk 8KB SMEM->GMEM copies
// (rows [bid*24, bid*24+24)). grid = 128 x 256.
// ---------------------------------------------------------------------------
__global__ __launch_bounds__(256) void k_broadcast(float* __restrict__ out)
{
    __shared__ alignas(128) float srow[N_NODES];    // 8 KB

    const int tid = threadIdx.x;
    const float4* pn4 = reinterpret_cast<const float4*>(g_per_node);
    float4* s4 = reinterpret_cast<float4*>(srow);
    #pragma unroll
    for (int i = tid; i < NF4; i += 256) s4[i] = __ldg(pn4 + i);
    __syncthreads();
    asm volatile("fence.proxy.async.shared::cta;" ::: "memory");

    if (tid == 0) {
        const unsigned saddr = smem_u32(srow);
        const int r0 = blockIdx.x * 24;
        #pragma unroll
        for (int r = 0; r < 24; r++) {
            float* g = out + (size_t)(r0 + r) * N_NODES;
            asm volatile(
                "cp.async.bulk.global.shared::cta.bulk_group [%0], [%1], %2;"
                :: "l"(g), "r"(saddr), "r"(8192) : "memory");
        }
        asm volatile("cp.async.bulk.commit_group;" ::: "memory");
        asm volatile("cp.async.bulk.wait_group 0;" ::: "memory");
    }
}

// ---------------------------------------------------------------------------
// Inputs: 0:x 1:edge_index(unused) 2:edge_attr(unused) 3:Wc 4:bc 5:W1 6:b1 7:W2 8:b2
// ---------------------------------------------------------------------------
extern "C" void kernel_launch(void* const* d_in, const int* in_sizes, int n_in,
                              void* d_out, int out_size)
{
    const float4* x4 = (const float4*)d_in[0];
    const float*  Wc = (const float*)d_in[3];
    const float*  bc = (const float*)d_in[4];
    const float*  W1 = (const float*)d_in[5];
    const float*  b1 = (const float*)d_in[6];
    const float*  W2 = (const float*)d_in[7];
    const float*  b2 = (const float*)d_in[8];
    float* out = (float*)d_out;

    k_gemm_partial<<<dim3(NBN, NKC), 256>>>(x4, Wc);
    k_reduce_mlp<<<32, 256>>>(bc, W1, b1, W2, b2);
    k_broadcast<<<128, 256>>>(out);
}